// round 13
// baseline (speedup 1.0000x reference)
#include <cuda_runtime.h>
#include <cuda_bf16.h>
#include <math.h>

#define NTOK 1568
#define CH 32
#define NPIX 256
#define NEXP 8
#define CAPN 245
#define NCLS 1000
#define HWD 224
#define HP 14
#define EPSV 1e-5f
#define PI_F 3.14159265358979323846f
#define PS2 328   /* u32 plane stride in smem; 328 % 32 == 8 */

typedef unsigned long long u64;

// ---- scratch (no allocations allowed) ----
__device__ unsigned g_tok32[NTOK * 16 * NPIX];   // bf16x2 {ci even, ci odd} per pixel (25.7 MB)
__device__ int   g_top1[NTOK];
__device__ float g_ptop[NTOK];
__device__ float g_lq[17 * NTOK];                // per-token loss partials, [q][n]
__device__ float g_wn[NTOK];
__device__ float g_psum[NTOK * CH];
__device__ float g_psumsq[NTOK * CH];
// bf16 mma A-fragments: [e][s(9)][mt(2)][kt(2)][lane(32)] uint4 (147 KB)
__device__ __align__(16) uint4 g_aw2[NEXP * 9 * 2 * 2 * 32];

// ---- f32x2 helpers (used by K1) ----
__device__ __forceinline__ u64 pack2(float x, float y) {
    u64 r; asm("mov.b64 %0, {%1, %2};" : "=l"(r) : "f"(x), "f"(y)); return r;
}
__device__ __forceinline__ void unpack2(u64 v, float& x, float& y) {
    asm("mov.b64 {%0, %1}, %2;" : "=f"(x), "=f"(y) : "l"(v));
}
__device__ __forceinline__ u64 ffma2(u64 a, u64 b, u64 c) {
    u64 d; asm("fma.rn.f32x2 %0, %1, %2, %3;" : "=l"(d) : "l"(a), "l"(b), "l"(c));
    return d;
}

// ---- bf16 helpers ----
__device__ __forceinline__ unsigned pack_bf2(float lo, float hi) {
    __nv_bfloat162 h = __floats2bfloat162_rn(lo, hi);
    return *(unsigned*)&h;
}
__device__ __forceinline__ float bf_sel(unsigned v, int par) {
    unsigned u = par ? (v >> 16) : (v & 0xffffu);
    unsigned short us = (unsigned short)u;
    __nv_bfloat16 h = *(__nv_bfloat16*)&us;
    return __bfloat162float(h);
}

// ---- bf16 mma m16n8k16 (row.col) ----
__device__ __forceinline__ void mma_bf16(float4& d, const uint4 a,
                                         unsigned b0, unsigned b1) {
    asm volatile(
        "mma.sync.aligned.m16n8k16.row.col.f32.bf16.bf16.f32 "
        "{%0,%1,%2,%3}, {%4,%5,%6,%7}, {%8,%9}, {%0,%1,%2,%3};\n"
        : "+f"(d.x), "+f"(d.y), "+f"(d.z), "+f"(d.w)
        : "r"(a.x), "r"(a.y), "r"(a.z), "r"(a.w), "r"(b0), "r"(b1));
}

// ============================================================
// K1: stem conv3x3 (3->32) + BN + SiLU -> packed bf16x2 tokens;
// channel means via smem transpose; FUSED gate + softmax + loss
// partials per token. Blocks 0..35 also emit mma A-fragments.
// ============================================================
__global__ void __launch_bounds__(256)
k1_stem(const float* __restrict__ X, const float* __restrict__ W,
        const float* __restrict__ bnw, const float* __restrict__ bnb,
        const float* __restrict__ EW,
        const float* __restrict__ gate_w, const float* __restrict__ gate_b) {
    __shared__ __align__(16) float sIn[3 * 18 * 18];
    __shared__ __align__(16) float sW[32 * 28];
    __shared__ float sBw[32], sBb[32];
    __shared__ float sTr[32 * 257];
    __shared__ float sP2[8 * 32];
    __shared__ float sGw[50 * 8];
    __shared__ float sGb[8];
    __shared__ float sCm[32];
    __shared__ float sFt[18];
    __shared__ float sLg[8];
    int n = blockIdx.x;
    int b = n / 196, pr = (n % 196) / HP, pc = n % HP;
    int tid = threadIdx.x;

    // bf16 A-fragment permutation fold (36*256 == 9216 entries)
    if (n < 36) {
        int i = n * 256 + tid;
        int lane2 = i & 31;
        int kt = (i >> 5) & 1;
        int mt = (i >> 6) & 1;
        int r  = i >> 7;           // e*9 + s
        int s  = r % 9;
        int e  = r / 9;
        int g = lane2 >> 2, c2 = (lane2 & 3) * 2;
        int m0 = mt * 16 + g;
        int ci0 = kt * 16 + c2;
        const float* base = EW + (size_t)e * 32 * 32 * 9 + s;
        #define AW(co, ci) base[((co) * 32 + (ci)) * 9]
        uint4 v;
        v.x = pack_bf2(AW(m0,     ci0),     AW(m0,     ci0 + 1));
        v.y = pack_bf2(AW(m0 + 8, ci0),     AW(m0 + 8, ci0 + 1));
        v.z = pack_bf2(AW(m0,     ci0 + 8), AW(m0,     ci0 + 9));
        v.w = pack_bf2(AW(m0 + 8, ci0 + 8), AW(m0 + 8, ci0 + 9));
        #undef AW
        g_aw2[i] = v;
    }

    for (int i = tid; i < 3 * 18 * 18; i += 256) {
        int ci = i / 324, r = (i % 324) / 18, c = i % 18;
        int gy = pr * 16 + r - 1, gx = pc * 16 + c - 1;
        float v = 0.f;
        if (gy >= 0 && gy < HWD && gx >= 0 && gx < HWD)
            v = X[((b * 3 + ci) * HWD + gy) * HWD + gx];
        sIn[i] = v;
    }
    for (int i = tid; i < 32 * 28; i += 256) {
        int co = i / 28, k = i % 28;
        sW[i] = (k < 27) ? W[co * 27 + k] : 0.f;
    }
    for (int i = tid; i < 400; i += 256) sGw[i] = gate_w[i];
    if (tid < 32) { sBw[tid] = bnw[tid]; sBb[tid] = bnb[tid]; }
    if (tid >= 32 && tid < 40) sGb[tid - 32] = gate_b[tid - 32];
    __syncthreads();

    int py = tid >> 4, px = tid & 15;
    float xin[28];
#pragma unroll
    for (int ci = 0; ci < 3; ci++)
#pragma unroll
        for (int dy = 0; dy < 3; dy++)
#pragma unroll
            for (int dx = 0; dx < 3; dx++)
                xin[ci * 9 + dy * 3 + dx] = sIn[ci * 324 + (py + dy) * 18 + (px + dx)];
    xin[27] = 0.f;
    u64 xp[14];
#pragma unroll
    for (int j = 0; j < 14; j++) xp[j] = pack2(xin[2 * j], xin[2 * j + 1]);

    unsigned* tok = g_tok32 + (size_t)n * 16 * NPIX + tid;
    for (int cp = 0; cp < 16; cp++) {
        const ulonglong2* w0 = (const ulonglong2*)(sW + (2 * cp) * 28);
        const ulonglong2* w1 = (const ulonglong2*)(sW + (2 * cp + 1) * 28);
        u64 acc0 = 0ULL, acc1 = 0ULL;
#pragma unroll
        for (int j = 0; j < 7; j++) {
            ulonglong2 wa = w0[j], wb = w1[j];
            acc0 = ffma2(wa.x, xp[2 * j], acc0);
            acc0 = ffma2(wa.y, xp[2 * j + 1], acc0);
            acc1 = ffma2(wb.x, xp[2 * j], acc1);
            acc1 = ffma2(wb.y, xp[2 * j + 1], acc1);
        }
        float a0, a1, b0, b1;
        unpack2(acc0, a0, a1);
        unpack2(acc1, b0, b1);
        float v0 = (a0 + a1) * sBw[2 * cp] + sBb[2 * cp];
        float v1 = (b0 + b1) * sBw[2 * cp + 1] + sBb[2 * cp + 1];
        float s0 = v0 / (1.f + __expf(-v0));
        float s1 = v1 / (1.f + __expf(-v1));
        tok[cp * NPIX] = pack_bf2(s0, s1);
        sTr[(2 * cp) * 257 + tid] = s0;
        sTr[(2 * cp + 1) * 257 + tid] = s1;
    }
    __syncthreads();
    // transpose reduction: 32 channels x 8 pixel-slices; plus Fourier feats
    {
        int co2 = tid & 31, j = tid >> 5;
        const float* p = sTr + co2 * 257 + j * 32;
        float sum = 0.f;
#pragma unroll
        for (int k = 0; k < 32; k++) sum += p[k];
        sP2[j * 32 + co2] = sum;
    }
    if (tid >= 64 && tid < 82) {
        int idx = tid - 64;
        float pv;
        if (idx == 0)      pv = (16.f * pr + 8.f) / 224.f;
        else if (idx == 1) pv = (16.f * pc + 8.f) / 224.f;
        else {
            int q = idx - 2;
            int k = q >> 2, sub = q & 3;
            int base = (sub < 2) ? pr : pc;
            float f = (float)(1 << k) * PI_F;
            float s = 0.f;
            for (int r = 0; r < 16; r++) {
                float ang = f * ((16.f * base + (float)r + 0.5f) / 224.f);
                s += (sub & 1) ? cosf(ang) : sinf(ang);
            }
            pv = s * (1.f / 16.f);
        }
        sFt[idx] = pv;
    }
    __syncthreads();
    if (tid < 32) {
        float sum = 0.f;
#pragma unroll
        for (int j = 0; j < 8; j++) sum += sP2[j * 32 + tid];
        sCm[tid] = sum * (1.f / 256.f);
    }
    __syncthreads();
    if (tid < 8) {
        float l = sGb[tid];
#pragma unroll
        for (int i = 0; i < 32; i++) l = fmaf(sCm[i], sGw[i * 8 + tid], l);
#pragma unroll
        for (int j = 0; j < 18; j++) l = fmaf(sFt[j], sGw[(32 + j) * 8 + tid], l);
        sLg[tid] = l;
    }
    __syncthreads();
    if (tid == 0) {
        float mx = sLg[0]; int am = 0;
#pragma unroll
        for (int e = 1; e < 8; e++) if (sLg[e] > mx) { mx = sLg[e]; am = e; }
        float pe[8], se = 0.f;
#pragma unroll
        for (int e = 0; e < 8; e++) { pe[e] = __expf(sLg[e] - mx); se += pe[e]; }
        float inv = 1.f / se;
        float lse = mx + __logf(se);
        g_top1[n] = am;
        g_ptop[n] = pe[am] * inv;
        g_lq[n] = lse * lse;
#pragma unroll
        for (int e = 0; e < 8; e++) {
            g_lq[(1 + e) * NTOK + n] = pe[e] * inv;
            g_lq[(9 + e) * NTOK + n] = (e == am) ? 1.f : 0.f;
        }
    }
}

// ============================================================
// K3: capacity scan (ballot, exact token order) + final losses
// ============================================================
__global__ void __launch_bounds__(512)
k3_dispatch(float* __restrict__ d_out) {
    __shared__ int   sT[NTOK];
    __shared__ int   sWC[16 * 9];
    __shared__ int   sRun[8];
    __shared__ float sWred[16][17];
    int tid = threadIdx.x;
    int lane = tid & 31, wid = tid >> 5;

    for (int i = tid; i < NTOK; i += 512) sT[i] = g_top1[i];
    if (tid < 8) sRun[tid] = 0;
    if (tid < 144) sWC[tid] = 0;
    __syncthreads();

    // loss partial accumulation (coalesced per q-plane)
    float part[17];
#pragma unroll
    for (int q = 0; q < 17; q++) {
        float s = 0.f;
        for (int n = tid; n < NTOK; n += 512) s += g_lq[q * NTOK + n];
        part[q] = s;
    }

    // capacity scan: chunked ballot prefix, exact token-index order
    for (int c = 0; c < 4; c++) {
        int n = c * 512 + tid;
        bool act = n < NTOK;
        int e = act ? sT[n] : 8;
        unsigned m = __match_any_sync(0xffffffffu, e);
        int lr = __popc(m & ((1u << lane) - 1u));
        if (lr == 0) sWC[wid * 9 + e] = __popc(m);
        __syncthreads();
        if (act) {
            int base = sRun[e];
            for (int w2 = 0; w2 < wid; w2++) base += sWC[w2 * 9 + e];
            int rank = base + lr;
            g_wn[n] = (rank < CAPN) ? g_ptop[n] : 0.f;
        }
        int s = 0;
        if (tid < 8) for (int w2 = 0; w2 < 16; w2++) s += sWC[w2 * 9 + tid];
        __syncthreads();
        if (tid < 8) sRun[tid] += s;
        if (tid < 144) sWC[tid] = 0;
        __syncthreads();
    }

    // loss reductions: warp shuffle + single cross-warp pass
#pragma unroll
    for (int q = 0; q < 17; q++) {
#pragma unroll
        for (int off = 16; off > 0; off >>= 1)
            part[q] += __shfl_down_sync(0xffffffffu, part[q], off);
        if (lane == 0) sWred[wid][q] = part[q];
    }
    __syncthreads();
    if (tid == 0) {
        float res[17];
#pragma unroll
        for (int q = 0; q < 17; q++) {
            float s = 0.f;
            for (int w2 = 0; w2 < 16; w2++) s += sWred[w2][q];
            res[q] = s;
        }
        float z = res[0] / (float)NTOK;
        float imb = 0.f;
        for (int e = 0; e < 8; e++) imb += res[1 + e] * res[9 + e];
        imb *= (float)NEXP / ((float)NTOK * (float)NTOK);
        d_out[8000] = z;
        d_out[8001] = imb;
    }
}

// ============================================================
// K4: expert conv3x3 via 9-shift bf16 m16n8k16 tensor-core GEMM.
// Image planes are bf16x2 channel pairs -> 1 LDS.32 per B-register.
// ============================================================
__global__ void __launch_bounds__(256, 4)
k4_expert(const float* __restrict__ EB, const float* __restrict__ gamma) {
    __shared__ __align__(16) unsigned sXp[16 * PS2];  // 16 cp-planes, 18x18 @ stride 18
    __shared__ float sPs[8][32], sPss[8][32];
    int n = blockIdx.x;
    int tid = threadIdx.x;
    float wn = g_wn[n];
    int e = g_top1[n];
    bool active = (wn != 0.f);
    int wid = tid >> 5, lane = tid & 31;
    int gid = lane >> 2, ctid = lane & 3;

    {
        u64* z = (u64*)sXp;
        for (int i = tid; i < 16 * PS2 / 2; i += 256) z[i] = 0ULL;
    }
    __syncthreads();
    {
        const uint4* src = (const uint4*)(g_tok32 + (size_t)n * 16 * NPIX);
#pragma unroll
        for (int it = 0; it < 4; it++) {
            int i = it * 256 + tid;          // uint4 = 4 pixels of one cp plane
            uint4 v = src[i];
            int cp = i >> 6;
            int p = (i & 63) * 4;
            unsigned* d = sXp + cp * PS2 + ((p >> 4) + 1) * 18 + (p & 15) + 1;
            d[0] = v.x; d[1] = v.y; d[2] = v.z; d[3] = v.w;
        }
    }
    __syncthreads();

    if (!active) {
        int row = lane >> 1, xb = (lane & 1) * 8;
#pragma unroll
        for (int c4 = 0; c4 < 4; c4++) {
            int co = wid * 4 + c4;
            int cp = co >> 1, par = co & 1;
            const unsigned* tp = sXp + cp * PS2 + (row + 1) * 18 + xb + 1;
            float s = 0.f, ss = 0.f;
#pragma unroll
            for (int p = 0; p < 8; p++) {
                float v = bf_sel(tp[p], par);
                s += v; ss = fmaf(v, v, ss);
            }
#pragma unroll
            for (int off = 16; off > 0; off >>= 1) {
                s  += __shfl_down_sync(0xffffffffu, s, off);
                ss += __shfl_down_sync(0xffffffffu, ss, off);
            }
            if (lane == 0) { g_psum[n * CH + co] = s; g_psumsq[n * CH + co] = ss; }
        }
        return;
    }

    float4 acc[2][4];
#pragma unroll
    for (int mt = 0; mt < 2; mt++)
#pragma unroll
        for (int nn = 0; nn < 4; nn++) acc[mt][nn] = make_float4(0.f, 0.f, 0.f, 0.f);

    int bIdx[4];
#pragma unroll
    for (int nn = 0; nn < 4; nn++)
        bIdx[nn] = ctid * PS2 + (wid * 2 + (nn >> 1)) * 18 + (nn & 1) * 8 + gid;
    const uint4* aBase = g_aw2 + (size_t)e * 1152 + lane;

#pragma unroll
    for (int ky = 0; ky < 3; ky++) {
#pragma unroll
        for (int kx = 0; kx < 3; kx++) {
            const int s = ky * 3 + kx;
#pragma unroll
            for (int kt = 0; kt < 2; kt++) {
                const int off = kt * (8 * PS2) + ky * 18 + kx;
                unsigned b0[4], b1[4];
#pragma unroll
                for (int nn = 0; nn < 4; nn++) {
                    b0[nn] = sXp[bIdx[nn] + off];
                    b1[nn] = sXp[bIdx[nn] + off + 4 * PS2];
                }
#pragma unroll
                for (int mt = 0; mt < 2; mt++) {
                    uint4 a = __ldg(aBase + ((s * 2 + mt) * 2 + kt) * 32);
#pragma unroll
                    for (int nn = 0; nn < 4; nn++)
                        mma_bf16(acc[mt][nn], a, b0[nn], b1[nn]);
                }
            }
        }
    }

    // epilogue: y = silu(D + b); v = t + gamma*wn*y; per-(warp,co) partial moments
#pragma unroll
    for (int mt = 0; mt < 2; mt++) {
#pragma unroll
        for (int half = 0; half < 2; half++) {
            int co = mt * 16 + gid + half * 8;
            int cp = co >> 1, par = co & 1;
            float bco = __ldg(EB + e * CH + co);
            float gm = __ldg(gamma + co) * wn;
            float s = 0.f, ss = 0.f;
#pragma unroll
            for (int nn = 0; nn < 4; nn++) {
                float y0 = half ? acc[mt][nn].z : acc[mt][nn].x;
                float y1 = half ? acc[mt][nn].w : acc[mt][nn].y;
                int r = wid * 2 + (nn >> 1);
                int x = (nn & 1) * 8 + 2 * ctid;
                const unsigned* tp = sXp + cp * PS2 + (r + 1) * 18 + x + 1;
                float t0 = bf_sel(tp[0], par);
                float t1 = bf_sel(tp[1], par);
                float a0 = y0 + bco; a0 = a0 / (1.f + __expf(-a0));
                float a1 = y1 + bco; a1 = a1 / (1.f + __expf(-a1));
                float v0 = t0 + gm * a0;
                float v1 = t1 + gm * a1;
                s += v0 + v1;
                ss = fmaf(v0, v0, ss);
                ss = fmaf(v1, v1, ss);
            }
            s  += __shfl_xor_sync(0xffffffffu, s, 1);
            s  += __shfl_xor_sync(0xffffffffu, s, 2);
            ss += __shfl_xor_sync(0xffffffffu, ss, 1);
            ss += __shfl_xor_sync(0xffffffffu, ss, 2);
            if (ctid == 0) { sPs[wid][co] = s; sPss[wid][co] = ss; }
        }
    }
    __syncthreads();
    if (tid < 32) {
        float S = 0.f, SS = 0.f;
#pragma unroll
        for (int w = 0; w < 8; w++) { S += sPs[w][tid]; SS += sPss[w][tid]; }
        g_psum[n * CH + tid] = S;
        g_psumsq[n * CH + tid] = SS;
    }
}

// ============================================================
// K5: GroupNorm(from moments) + pool + LayerNorm + head
// ============================================================
__global__ void __launch_bounds__(1024)
k5_head(const float* __restrict__ gnw, const float* __restrict__ gnb,
        const float* __restrict__ lnw, const float* __restrict__ lnb,
        const float* __restrict__ hw, const float* __restrict__ hb,
        float* __restrict__ d_out) {
    __shared__ float sS32[32 * 32], sSS32[32 * 32];
    __shared__ float sS[32], sF[32], sFN[32];
    __shared__ float sMg[8], sRg[8];
    int b = blockIdx.x, tid = threadIdx.x;
    {
        int c = tid & 31, sl = tid >> 5;
        float S = 0.f, SS = 0.f;
        for (int t = sl; t < 196; t += 32) {
            int idx = (b * 196 + t) * CH + c;
            S += g_psum[idx]; SS += g_psumsq[idx];
        }
        sS32[sl * 32 + c] = S; sSS32[sl * 32 + c] = SS;
    }
    __syncthreads();
    if (tid < 32) {
        float S = 0.f, SS = 0.f;
#pragma unroll
        for (int sl = 0; sl < 32; sl++) { S += sS32[sl * 32 + tid]; SS += sSS32[sl * 32 + tid]; }
        sS[tid] = S; sS32[tid] = S; sSS32[tid] = SS;
    }
    __syncthreads();
    if (tid < 8) {
        float S  = sS32[tid * 4] + sS32[tid * 4 + 1] + sS32[tid * 4 + 2] + sS32[tid * 4 + 3];
        float SS = sSS32[tid * 4] + sSS32[tid * 4 + 1] + sSS32[tid * 4 + 2] + sSS32[tid * 4 + 3];
        const float inv = 1.f / (4.f * 50176.f);
        float m = S * inv;
        float ex2 = SS * inv;
        sMg[tid] = m;
        sRg[tid] = rsqrtf(ex2 - m * m + EPSV);
    }
    __syncthreads();
    if (tid < 32) {
        float mx = sS[tid] * (1.f / 50176.f);
        int g = tid >> 2;
        sF[tid] = (mx - sMg[g]) * sRg[g] * gnw[tid] + gnb[tid];
    }
    __syncthreads();
    if (tid == 0) {
        float mu = 0.f;
        for (int c = 0; c < 32; c++) mu += sF[c];
        mu *= (1.f / 32.f);
        float va = 0.f;
        for (int c = 0; c < 32; c++) { float d = sF[c] - mu; va = fmaf(d, d, va); }
        va *= (1.f / 32.f);
        float r = rsqrtf(va + EPSV);
        for (int c = 0; c < 32; c++) sFN[c] = (sF[c] - mu) * r * lnw[c] + lnb[c];
    }
    __syncthreads();
    for (int j = tid; j < NCLS; j += 1024) {
        float a = hb[j];
#pragma unroll
        for (int c = 0; c < 32; c++) a = fmaf(sFN[c], hw[c * NCLS + j], a);
        d_out[b * NCLS + j] = a;
    }
}

// ============================================================
extern "C" void kernel_launch(void* const* d_in, const int* in_sizes, int n_in,
                              void* d_out, int out_size) {
    const float* X        = (const float*)d_in[0];
    const float* stem_w   = (const float*)d_in[1];
    const float* bn_w     = (const float*)d_in[2];
    const float* bn_b     = (const float*)d_in[3];
    const float* gate_w   = (const float*)d_in[4];
    const float* gate_b   = (const float*)d_in[5];
    const float* expert_w = (const float*)d_in[6];
    const float* expert_b = (const float*)d_in[7];
    const float* gamma    = (const float*)d_in[8];
    const float* gn_w     = (const float*)d_in[9];
    const float* gn_b     = (const float*)d_in[10];
    const float* ln_w     = (const float*)d_in[11];
    const float* ln_b     = (const float*)d_in[12];
    const float* head_w   = (const float*)d_in[13];
    const float* head_b   = (const float*)d_in[14];
    float* out = (float*)d_out;

    k1_stem<<<NTOK, 256>>>(X, stem_w, bn_w, bn_b, expert_w, gate_w, gate_b);
    k3_dispatch<<<1, 512>>>(out);
    k4_expert<<<NTOK, 256>>>(expert_b, gamma);
    k5_head<<<8, 1024>>>(gn_w, gn_b, ln_w, ln_b, head_w, head_b, out);
}

// round 15
// speedup vs baseline: 1.2604x; 1.2604x over previous
#include <cuda_runtime.h>
#include <cuda_bf16.h>
#include <math.h>

#define NTOK 1568
#define CH 32
#define NPIX 256
#define NEXP 8
#define CAPN 245
#define NCLS 1000
#define HWD 224
#define HP 14
#define EPSV 1e-5f
#define PI_F 3.14159265358979323846f
#define PS2 328   /* u32 plane stride in smem; 328 % 32 == 8 */

typedef unsigned long long u64;

// ---- scratch (no allocations allowed) ----
__device__ unsigned g_tok32[NTOK * 16 * NPIX];   // bf16x2 {ci even, ci odd} per pixel (25.7 MB)
__device__ float g_cmean[NTOK * CH];
__device__ int   g_top1[NTOK];
__device__ float g_ptop[NTOK];
__device__ float g_lpart[13 * 17];
__device__ float g_wn[NTOK];
__device__ float g_psum[NTOK * CH];
__device__ float g_psumsq[NTOK * CH];
// bf16 mma A-fragments: [e][s(9)][mt(2)][kt(2)][lane(32)] uint4 (147 KB)
__device__ __align__(16) uint4 g_aw2[NEXP * 9 * 2 * 2 * 32];

// ---- f32x2 helpers (used by K1) ----
__device__ __forceinline__ u64 pack2(float x, float y) {
    u64 r; asm("mov.b64 %0, {%1, %2};" : "=l"(r) : "f"(x), "f"(y)); return r;
}
__device__ __forceinline__ void unpack2(u64 v, float& x, float& y) {
    asm("mov.b64 {%0, %1}, %2;" : "=f"(x), "=f"(y) : "l"(v));
}
__device__ __forceinline__ u64 ffma2(u64 a, u64 b, u64 c) {
    u64 d; asm("fma.rn.f32x2 %0, %1, %2, %3;" : "=l"(d) : "l"(a), "l"(b), "l"(c));
    return d;
}

// ---- bf16 helpers ----
__device__ __forceinline__ unsigned pack_bf2(float lo, float hi) {
    __nv_bfloat162 h = __floats2bfloat162_rn(lo, hi);
    return *(unsigned*)&h;
}
__device__ __forceinline__ float bf_sel(unsigned v, int par) {
    unsigned u = par ? (v >> 16) : (v & 0xffffu);
    unsigned short us = (unsigned short)u;
    __nv_bfloat16 h = *(__nv_bfloat16*)&us;
    return __bfloat162float(h);
}

// ---- bf16 mma m16n8k16 (row.col) ----
__device__ __forceinline__ void mma_bf16(float4& d, const uint4 a,
                                         unsigned b0, unsigned b1) {
    asm volatile(
        "mma.sync.aligned.m16n8k16.row.col.f32.bf16.bf16.f32 "
        "{%0,%1,%2,%3}, {%4,%5,%6,%7}, {%8,%9}, {%0,%1,%2,%3};\n"
        : "+f"(d.x), "+f"(d.y), "+f"(d.z), "+f"(d.w)
        : "r"(a.x), "r"(a.y), "r"(a.z), "r"(a.w), "r"(b0), "r"(b1));
}

// ============================================================
// K1: stem conv3x3 (3->32) + BN + SiLU -> packed bf16x2 tokens;
// channel means via smem transpose. Blocks 0..35 emit A-fragments.
// ============================================================
__global__ void __launch_bounds__(256)
k1_stem(const float* __restrict__ X, const float* __restrict__ W,
        const float* __restrict__ bnw, const float* __restrict__ bnb,
        const float* __restrict__ EW) {
    __shared__ __align__(16) float sIn[3 * 18 * 18];
    __shared__ __align__(16) float sW[32 * 28];
    __shared__ float sBw[32], sBb[32];
    __shared__ float sTr[32 * 257];
    __shared__ float sP2[8 * 32];
    int n = blockIdx.x;
    int b = n / 196, pr = (n % 196) / HP, pc = n % HP;
    int tid = threadIdx.x;

    // bf16 A-fragment permutation fold (36*256 == 9216 entries)
    if (n < 36) {
        int i = n * 256 + tid;
        int lane2 = i & 31;
        int kt = (i >> 5) & 1;
        int mt = (i >> 6) & 1;
        int r  = i >> 7;           // e*9 + s
        int s  = r % 9;
        int e  = r / 9;
        int g = lane2 >> 2, c2 = (lane2 & 3) * 2;
        int m0 = mt * 16 + g;
        int ci0 = kt * 16 + c2;
        const float* base = EW + (size_t)e * 32 * 32 * 9 + s;
        #define AW(co, ci) base[((co) * 32 + (ci)) * 9]
        uint4 v;
        v.x = pack_bf2(AW(m0,     ci0),     AW(m0,     ci0 + 1));
        v.y = pack_bf2(AW(m0 + 8, ci0),     AW(m0 + 8, ci0 + 1));
        v.z = pack_bf2(AW(m0,     ci0 + 8), AW(m0,     ci0 + 9));
        v.w = pack_bf2(AW(m0 + 8, ci0 + 8), AW(m0 + 8, ci0 + 9));
        #undef AW
        g_aw2[i] = v;
    }

    for (int i = tid; i < 3 * 18 * 18; i += 256) {
        int ci = i / 324, r = (i % 324) / 18, c = i % 18;
        int gy = pr * 16 + r - 1, gx = pc * 16 + c - 1;
        float v = 0.f;
        if (gy >= 0 && gy < HWD && gx >= 0 && gx < HWD)
            v = X[((b * 3 + ci) * HWD + gy) * HWD + gx];
        sIn[i] = v;
    }
    for (int i = tid; i < 32 * 28; i += 256) {
        int co = i / 28, k = i % 28;
        sW[i] = (k < 27) ? W[co * 27 + k] : 0.f;
    }
    if (tid < 32) { sBw[tid] = bnw[tid]; sBb[tid] = bnb[tid]; }
    __syncthreads();

    int py = tid >> 4, px = tid & 15;
    float xin[28];
#pragma unroll
    for (int ci = 0; ci < 3; ci++)
#pragma unroll
        for (int dy = 0; dy < 3; dy++)
#pragma unroll
            for (int dx = 0; dx < 3; dx++)
                xin[ci * 9 + dy * 3 + dx] = sIn[ci * 324 + (py + dy) * 18 + (px + dx)];
    xin[27] = 0.f;
    u64 xp[14];
#pragma unroll
    for (int j = 0; j < 14; j++) xp[j] = pack2(xin[2 * j], xin[2 * j + 1]);

    unsigned* tok = g_tok32 + (size_t)n * 16 * NPIX + tid;
    for (int cp = 0; cp < 16; cp++) {
        const ulonglong2* w0 = (const ulonglong2*)(sW + (2 * cp) * 28);
        const ulonglong2* w1 = (const ulonglong2*)(sW + (2 * cp + 1) * 28);
        u64 acc0 = 0ULL, acc1 = 0ULL;
#pragma unroll
        for (int j = 0; j < 7; j++) {
            ulonglong2 wa = w0[j], wb = w1[j];
            acc0 = ffma2(wa.x, xp[2 * j], acc0);
            acc0 = ffma2(wa.y, xp[2 * j + 1], acc0);
            acc1 = ffma2(wb.x, xp[2 * j], acc1);
            acc1 = ffma2(wb.y, xp[2 * j + 1], acc1);
        }
        float a0, a1, b0, b1;
        unpack2(acc0, a0, a1);
        unpack2(acc1, b0, b1);
        float v0 = (a0 + a1) * sBw[2 * cp] + sBb[2 * cp];
        float v1 = (b0 + b1) * sBw[2 * cp + 1] + sBb[2 * cp + 1];
        float s0 = v0 / (1.f + __expf(-v0));
        float s1 = v1 / (1.f + __expf(-v1));
        tok[cp * NPIX] = pack_bf2(s0, s1);
        sTr[(2 * cp) * 257 + tid] = s0;
        sTr[(2 * cp + 1) * 257 + tid] = s1;
    }
    __syncthreads();
    // transpose reduction: 32 channels x 8 pixel-slices
    {
        int co2 = tid & 31, j = tid >> 5;
        const float* p = sTr + co2 * 257 + j * 32;
        float sum = 0.f;
#pragma unroll
        for (int k = 0; k < 32; k++) sum += p[k];
        sP2[j * 32 + co2] = sum;
    }
    __syncthreads();
    if (tid < 32) {
        float sum = 0.f;
#pragma unroll
        for (int j = 0; j < 8; j++) sum += sP2[j * 32 + tid];
        g_cmean[n * CH + tid] = sum * (1.f / 256.f);
    }
}

// ============================================================
// K2: gate (one thread/token) + per-block loss partials -> g_lpart
// ============================================================
__global__ void __launch_bounds__(128)
k2_gate(const float* __restrict__ gate_w, const float* __restrict__ gate_b) {
    __shared__ float sGw[50 * 8];
    __shared__ float sGb[8];
    __shared__ float tab[14][9];
    __shared__ float sRed[4][17];
    int tid = threadIdx.x;
    int lane = tid & 31, wid = tid >> 5;

    for (int i = tid; i < 400; i += 128) sGw[i] = gate_w[i];
    if (tid < 8) sGb[tid] = gate_b[tid];
    if (tid < 56) {
        int b2 = tid >> 2, k = tid & 3;
        float f = (float)(1 << k) * PI_F;
        float ss = 0.f, cs = 0.f;
        for (int r = 0; r < 16; r++) {
            float ang = f * ((16.f * b2 + (float)r + 0.5f) / 224.f);
            ss += sinf(ang); cs += cosf(ang);
        }
        tab[b2][1 + 2 * k] = ss * (1.f / 16.f);
        tab[b2][2 + 2 * k] = cs * (1.f / 16.f);
    } else if (tid < 70) {
        int b2 = tid - 56;
        tab[b2][0] = (16.f * b2 + 8.f) / 224.f;
    }
    __syncthreads();

    int n = blockIdx.x * 128 + tid;
    bool act = n < NTOK;
    float part[17];
#pragma unroll
    for (int q = 0; q < 17; q++) part[q] = 0.f;

    if (act) {
        int pr = (n % 196) / HP, pc = n % HP;
        float l[8];
#pragma unroll
        for (int e = 0; e < 8; e++) l[e] = sGb[e];
        const float4* cm4 = (const float4*)&g_cmean[n * CH];
#pragma unroll
        for (int i4 = 0; i4 < 8; i4++) {
            float4 v4 = cm4[i4];
            float vv[4] = {v4.x, v4.y, v4.z, v4.w};
#pragma unroll
            for (int q = 0; q < 4; q++) {
                int i = i4 * 4 + q;
#pragma unroll
                for (int e = 0; e < 8; e++) l[e] = fmaf(vv[q], sGw[i * 8 + e], l[e]);
            }
        }
        {
            float v0 = tab[pr][0], v1 = tab[pc][0];
#pragma unroll
            for (int e = 0; e < 8; e++) {
                l[e] = fmaf(v0, sGw[32 * 8 + e], l[e]);
                l[e] = fmaf(v1, sGw[33 * 8 + e], l[e]);
            }
        }
#pragma unroll
        for (int k = 0; k < 4; k++) {
#pragma unroll
            for (int sub = 0; sub < 4; sub++) {
                float v = (sub < 2) ? tab[pr][1 + 2 * k + sub] : tab[pc][1 + 2 * k + (sub - 2)];
#pragma unroll
                for (int e = 0; e < 8; e++)
                    l[e] = fmaf(v, sGw[(34 + 4 * k + sub) * 8 + e], l[e]);
            }
        }
        float mx = l[0]; int am = 0;
#pragma unroll
        for (int e = 1; e < 8; e++) if (l[e] > mx) { mx = l[e]; am = e; }
        float pe[8], se = 0.f;
#pragma unroll
        for (int e = 0; e < 8; e++) { pe[e] = __expf(l[e] - mx); se += pe[e]; }
        float inv = 1.f / se;
        float lse = mx + __logf(se);
        part[0] = lse * lse;
#pragma unroll
        for (int e = 0; e < 8; e++) part[1 + e] = pe[e] * inv;
        part[9 + am] = 1.f;
        g_top1[n] = am;
        g_ptop[n] = pe[am] * inv;
    }

#pragma unroll
    for (int q = 0; q < 17; q++) {
#pragma unroll
        for (int off = 16; off > 0; off >>= 1)
            part[q] += __shfl_down_sync(0xffffffffu, part[q], off);
        if (lane == 0) sRed[wid][q] = part[q];
    }
    __syncthreads();
    if (tid < 17)
        g_lpart[blockIdx.x * 17 + tid] =
            sRed[0][tid] + sRed[1][tid] + sRed[2][tid] + sRed[3][tid];
}

// ============================================================
// K3: capacity scan (ballot, exact token order) + final losses
// ============================================================
__global__ void __launch_bounds__(512)
k3_dispatch(float* __restrict__ d_out) {
    __shared__ int   sT[NTOK];
    __shared__ int   sWC[16 * 9];
    __shared__ int   sRun[8];
    __shared__ float sRes[17];
    int tid = threadIdx.x;
    int lane = tid & 31, wid = tid >> 5;

    for (int i = tid; i < NTOK; i += 512) sT[i] = g_top1[i];
    if (tid < 8) sRun[tid] = 0;
    if (tid < 144) sWC[tid] = 0;
    if (tid >= 256 && tid < 256 + 17) {
        int q = tid - 256;
        float s = 0.f;
        for (int b2 = 0; b2 < 13; b2++) s += g_lpart[b2 * 17 + q];
        sRes[q] = s;
    }
    __syncthreads();

    for (int c = 0; c < 4; c++) {
        int n = c * 512 + tid;
        bool act = n < NTOK;
        int e = act ? sT[n] : 8;
        unsigned m = __match_any_sync(0xffffffffu, e);
        int lr = __popc(m & ((1u << lane) - 1u));
        if (lr == 0) sWC[wid * 9 + e] = __popc(m);
        __syncthreads();
        if (act) {
            int base = sRun[e];
            for (int w2 = 0; w2 < wid; w2++) base += sWC[w2 * 9 + e];
            int rank = base + lr;
            g_wn[n] = (rank < CAPN) ? g_ptop[n] : 0.f;
        }
        int s = 0;
        if (tid < 8) for (int w2 = 0; w2 < 16; w2++) s += sWC[w2 * 9 + tid];
        __syncthreads();
        if (tid < 8) sRun[tid] += s;
        if (tid < 144) sWC[tid] = 0;
        __syncthreads();
    }

    if (tid == 0) {
        float z = sRes[0] / (float)NTOK;
        float imb = 0.f;
        for (int e = 0; e < 8; e++) imb += sRes[1 + e] * sRes[9 + e];
        imb *= (float)NEXP / ((float)NTOK * (float)NTOK);
        d_out[8000] = z;
        d_out[8001] = imb;
    }
}

// ============================================================
// K4: expert conv3x3 via 9-shift bf16 m16n8k16 tensor-core GEMM.
// cp.async pipelined fill: K-tile 0 planes computed while K-tile 1
// planes stream in. Halo-only zero-fill.
// ============================================================
__device__ __forceinline__ void k4_compute_kt(
    const unsigned* __restrict__ sXp, const uint4* __restrict__ aBase,
    const int bIdx[4], int kt, float4 acc[2][4]) {
#pragma unroll
    for (int ky = 0; ky < 3; ky++) {
#pragma unroll
        for (int kx = 0; kx < 3; kx++) {
            const int s = ky * 3 + kx;
            const int off = kt * (8 * PS2) + ky * 18 + kx;
            unsigned b0[4], b1[4];
#pragma unroll
            for (int nn = 0; nn < 4; nn++) {
                b0[nn] = sXp[bIdx[nn] + off];
                b1[nn] = sXp[bIdx[nn] + off + 4 * PS2];
            }
#pragma unroll
            for (int mt = 0; mt < 2; mt++) {
                uint4 a = __ldg(aBase + ((s * 2 + mt) * 2 + kt) * 32);
#pragma unroll
                for (int nn = 0; nn < 4; nn++)
                    mma_bf16(acc[mt][nn], a, b0[nn], b1[nn]);
            }
        }
    }
}

__global__ void __launch_bounds__(256, 3)
k4_expert(const float* __restrict__ EB, const float* __restrict__ gamma) {
    __shared__ __align__(16) unsigned sXp[16 * PS2];  // 16 cp-planes, 18x18 @ stride 18
    __shared__ float sPs[8][32], sPss[8][32];
    int n = blockIdx.x;
    int tid = threadIdx.x;
    float wn = g_wn[n];
    int e = g_top1[n];
    bool active = (wn != 0.f);
    int wid = tid >> 5, lane = tid & 31;
    int gid = lane >> 2, ctid = lane & 3;

    // async fill: group A = planes 0-7 (it 0,1), group B = planes 8-15 (it 2,3)
    {
        const unsigned* src = g_tok32 + (size_t)n * 16 * NPIX;
        unsigned sbase = (unsigned)__cvta_generic_to_shared(sXp);
#pragma unroll
        for (int it = 0; it < 4; it++) {
            int i = it * 256 + tid;          // u32-quad index
            int cp = i >> 6;
            int p = (i & 63) * 4;
            unsigned daddr = sbase +
                (unsigned)(cp * PS2 + ((p >> 4) + 1) * 18 + (p & 15) + 1) * 4u;
            const unsigned* gp = src + i * 4;
#pragma unroll
            for (int q = 0; q < 4; q++)
                asm volatile("cp.async.ca.shared.global [%0], [%1], 4;"
                             :: "r"(daddr + 4u * q), "l"(gp + q));
            if (it == 1 || it == 3)
                asm volatile("cp.async.commit_group;" ::: "memory");
        }
    }
    // halo-only zero (interior is fully overwritten by the async fill)
    for (int i = tid; i < 16 * 68; i += 256) {
        int cp = i / 68, j = i % 68;
        int row, col;
        if (j < 18)      { row = 0;      col = j; }
        else if (j < 36) { row = 17;     col = j - 18; }
        else if (j < 52) { row = j - 35; col = 0; }
        else             { row = j - 51; col = 17; }
        sXp[cp * PS2 + row * 18 + col] = 0u;
    }

    asm volatile("cp.async.wait_group 1;" ::: "memory");
    __syncthreads();          // planes 0-7 + halo visible block-wide

    if (!active) {
        asm volatile("cp.async.wait_group 0;" ::: "memory");
        __syncthreads();
        int row = lane >> 1, xb = (lane & 1) * 8;
#pragma unroll
        for (int c4 = 0; c4 < 4; c4++) {
            int co = wid * 4 + c4;
            int cp = co >> 1, par = co & 1;
            const unsigned* tp = sXp + cp * PS2 + (row + 1) * 18 + xb + 1;
            float s = 0.f, ss = 0.f;
#pragma unroll
            for (int p = 0; p < 8; p++) {
                float v = bf_sel(tp[p], par);
                s += v; ss = fmaf(v, v, ss);
            }
#pragma unroll
            for (int off = 16; off > 0; off >>= 1) {
                s  += __shfl_down_sync(0xffffffffu, s, off);
                ss += __shfl_down_sync(0xffffffffu, ss, off);
            }
            if (lane == 0) { g_psum[n * CH + co] = s; g_psumsq[n * CH + co] = ss; }
        }
        return;
    }

    float4 acc[2][4];
#pragma unroll
    for (int mt = 0; mt < 2; mt++)
#pragma unroll
        for (int nn = 0; nn < 4; nn++) acc[mt][nn] = make_float4(0.f, 0.f, 0.f, 0.f);

    int bIdx[4];
#pragma unroll
    for (int nn = 0; nn < 4; nn++)
        bIdx[nn] = ctid * PS2 + (wid * 2 + (nn >> 1)) * 18 + (nn & 1) * 8 + gid;
    const uint4* aBase = g_aw2 + (size_t)e * 1152 + lane;

    k4_compute_kt(sXp, aBase, bIdx, 0, acc);       // planes 0-7
    asm volatile("cp.async.wait_group 0;" ::: "memory");
    __syncthreads();                               // planes 8-15 visible
    k4_compute_kt(sXp, aBase, bIdx, 1, acc);       // planes 8-15

    // epilogue: y = silu(D + b); v = t + gamma*wn*y; per-(warp,co) partial moments
#pragma unroll
    for (int mt = 0; mt < 2; mt++) {
#pragma unroll
        for (int half = 0; half < 2; half++) {
            int co = mt * 16 + gid + half * 8;
            int cp = co >> 1, par = co & 1;
            float bco = __ldg(EB + e * CH + co);
            float gm = __ldg(gamma + co) * wn;
            float s = 0.f, ss = 0.f;
#pragma unroll
            for (int nn = 0; nn < 4; nn++) {
                float y0 = half ? acc[mt][nn].z : acc[mt][nn].x;
                float y1 = half ? acc[mt][nn].w : acc[mt][nn].y;
                int r = wid * 2 + (nn >> 1);
                int x = (nn & 1) * 8 + 2 * ctid;
                const unsigned* tp = sXp + cp * PS2 + (r + 1) * 18 + x + 1;
                float t0 = bf_sel(tp[0], par);
                float t1 = bf_sel(tp[1], par);
                float a0 = y0 + bco; a0 = a0 / (1.f + __expf(-a0));
                float a1 = y1 + bco; a1 = a1 / (1.f + __expf(-a1));
                float v0 = t0 + gm * a0;
                float v1 = t1 + gm * a1;
                s += v0 + v1;
                ss = fmaf(v0, v0, ss);
                ss = fmaf(v1, v1, ss);
            }
            s  += __shfl_xor_sync(0xffffffffu, s, 1);
            s  += __shfl_xor_sync(0xffffffffu, s, 2);
            ss += __shfl_xor_sync(0xffffffffu, ss, 1);
            ss += __shfl_xor_sync(0xffffffffu, ss, 2);
            if (ctid == 0) { sPs[wid][co] = s; sPss[wid][co] = ss; }
        }
    }
    __syncthreads();
    if (tid < 32) {
        float S = 0.f, SS = 0.f;
#pragma unroll
        for (int w = 0; w < 8; w++) { S += sPs[w][tid]; SS += sPss[w][tid]; }
        g_psum[n * CH + tid] = S;
        g_psumsq[n * CH + tid] = SS;
    }
}

// ============================================================
// K5: GroupNorm(from moments) + pool + LayerNorm + head
// ============================================================
__global__ void __launch_bounds__(1024)
k5_head(const float* __restrict__ gnw, const float* __restrict__ gnb,
        const float* __restrict__ lnw, const float* __restrict__ lnb,
        const float* __restrict__ hw, const float* __restrict__ hb,
        float* __restrict__ d_out) {
    __shared__ float sS32[32 * 32], sSS32[32 * 32];
    __shared__ float sS[32], sF[32], sFN[32];
    __shared__ float sMg[8], sRg[8];
    int b = blockIdx.x, tid = threadIdx.x;
    {
        int c = tid & 31, sl = tid >> 5;
        float S = 0.f, SS = 0.f;
        for (int t = sl; t < 196; t += 32) {
            int idx = (b * 196 + t) * CH + c;
            S += g_psum[idx]; SS += g_psumsq[idx];
        }
        sS32[sl * 32 + c] = S; sSS32[sl * 32 + c] = SS;
    }
    __syncthreads();
    if (tid < 32) {
        float S = 0.f, SS = 0.f;
#pragma unroll
        for (int sl = 0; sl < 32; sl++) { S += sS32[sl * 32 + tid]; SS += sSS32[sl * 32 + tid]; }
        sS[tid] = S; sS32[tid] = S; sSS32[tid] = SS;
    }
    __syncthreads();
    if (tid < 8) {
        float S  = sS32[tid * 4] + sS32[tid * 4 + 1] + sS32[tid * 4 + 2] + sS32[tid * 4 + 3];
        float SS = sSS32[tid * 4] + sSS32[tid * 4 + 1] + sSS32[tid * 4 + 2] + sSS32[tid * 4 + 3];
        const float inv = 1.f / (4.f * 50176.f);
        float m = S * inv;
        float ex2 = SS * inv;
        sMg[tid] = m;
        sRg[tid] = rsqrtf(ex2 - m * m + EPSV);
    }
    __syncthreads();
    if (tid < 32) {
        float mx = sS[tid] * (1.f / 50176.f);
        int g = tid >> 2;
        sF[tid] = (mx - sMg[g]) * sRg[g] * gnw[tid] + gnb[tid];
    }
    __syncthreads();
    if (tid == 0) {
        float mu = 0.f;
        for (int c = 0; c < 32; c++) mu += sF[c];
        mu *= (1.f / 32.f);
        float va = 0.f;
        for (int c = 0; c < 32; c++) { float d = sF[c] - mu; va = fmaf(d, d, va); }
        va *= (1.f / 32.f);
        float r = rsqrtf(va + EPSV);
        for (int c = 0; c < 32; c++) sFN[c] = (sF[c] - mu) * r * lnw[c] + lnb[c];
    }
    __syncthreads();
    for (int j = tid; j < NCLS; j += 1024) {
        float a = hb[j];
#pragma unroll
        for (int c = 0; c < 32; c++) a = fmaf(sFN[c], hw[c * NCLS + j], a);
        d_out[b * NCLS + j] = a;
    }
}

// ============================================================
extern "C" void kernel_launch(void* const* d_in, const int* in_sizes, int n_in,
                              void* d_out, int out_size) {
    const float* X        = (const float*)d_in[0];
    const float* stem_w   = (const float*)d_in[1];
    const float* bn_w     = (const float*)d_in[2];
    const float* bn_b     = (const float*)d_in[3];
    const float* gate_w   = (const float*)d_in[4];
    const float* gate_b   = (const float*)d_in[5];
    const float* expert_w = (const float*)d_in[6];
    const float* expert_b = (const float*)d_in[7];
    const float* gamma    = (const float*)d_in[8];
    const float* gn_w     = (const float*)d_in[9];
    const float* gn_b     = (const float*)d_in[10];
    const float* ln_w     = (const float*)d_in[11];
    const float* ln_b     = (const float*)d_in[12];
    const float* head_w   = (const float*)d_in[13];
    const float* head_b   = (const float*)d_in[14];
    float* out = (float*)d_out;

    k1_stem<<<NTOK, 256>>>(X, stem_w, bn_w, bn_b, expert_w);
    k2_gate<<<(NTOK + 127) / 128, 128>>>(gate_w, gate_b);
    k3_dispatch<<<1, 512>>>(out);
    k4_expert<<<NTOK, 256>>>(expert_b, gamma);
    k5_head<<<8, 1024>>>(gn_w, gn_b, ln_w, ln_b, head_w, head_b, out);
}

// round 16
// speedup vs baseline: 1.2884x; 1.0222x over previous
#include <cuda_runtime.h>
#include <cuda_bf16.h>
#include <math.h>

#define NTOK 1568
#define CH 32
#define NPIX 256
#define NEXP 8
#define CAPN 245
#define NCLS 1000
#define HWD 224
#define HP 14
#define EPSV 1e-5f
#define PI_F 3.14159265358979323846f
#define RS 24     /* u32 row stride in K4 smem plane */
#define PS2 440   /* u32 plane stride in K4 smem; 440 % 32 == 24 */
#define CBASE 4   /* interior pixel x=0 sits at col 4 (16B aligned) */

typedef unsigned long long u64;

// ---- scratch (no allocations allowed) ----
__device__ __align__(16) unsigned g_tok32[NTOK * 16 * NPIX];  // bf16x2 {ci even, ci odd} per pixel
__device__ float g_cmean[NTOK * CH];
__device__ int   g_top1[NTOK];
__device__ float g_ptop[NTOK];
__device__ float g_lpart[13 * 17];
__device__ float g_wn[NTOK];
__device__ float g_psum[NTOK * CH];
__device__ float g_psumsq[NTOK * CH];
// bf16 mma A-fragments: [e][s(9)][mt(2)][kt(2)][lane(32)] uint4 (147 KB)
__device__ __align__(16) uint4 g_aw2[NEXP * 9 * 2 * 2 * 32];

// ---- f32x2 helpers (used by K1) ----
__device__ __forceinline__ u64 pack2(float x, float y) {
    u64 r; asm("mov.b64 %0, {%1, %2};" : "=l"(r) : "f"(x), "f"(y)); return r;
}
__device__ __forceinline__ void unpack2(u64 v, float& x, float& y) {
    asm("mov.b64 {%0, %1}, %2;" : "=f"(x), "=f"(y) : "l"(v));
}
__device__ __forceinline__ u64 ffma2(u64 a, u64 b, u64 c) {
    u64 d; asm("fma.rn.f32x2 %0, %1, %2, %3;" : "=l"(d) : "l"(a), "l"(b), "l"(c));
    return d;
}

// ---- bf16 helpers ----
__device__ __forceinline__ unsigned pack_bf2(float lo, float hi) {
    __nv_bfloat162 h = __floats2bfloat162_rn(lo, hi);
    return *(unsigned*)&h;
}
__device__ __forceinline__ float bf_sel(unsigned v, int par) {
    unsigned u = par ? (v >> 16) : (v & 0xffffu);
    unsigned short us = (unsigned short)u;
    __nv_bfloat16 h = *(__nv_bfloat16*)&us;
    return __bfloat162float(h);
}

// ---- bf16 mma m16n8k16 (row.col) ----
__device__ __forceinline__ void mma_bf16(float4& d, const uint4 a,
                                         unsigned b0, unsigned b1) {
    asm volatile(
        "mma.sync.aligned.m16n8k16.row.col.f32.bf16.bf16.f32 "
        "{%0,%1,%2,%3}, {%4,%5,%6,%7}, {%8,%9}, {%0,%1,%2,%3};\n"
        : "+f"(d.x), "+f"(d.y), "+f"(d.z), "+f"(d.w)
        : "r"(a.x), "r"(a.y), "r"(a.z), "r"(a.w), "r"(b0), "r"(b1));
}

// ============================================================
// K1: stem conv3x3 (3->32) + BN + SiLU -> packed bf16x2 tokens;
// channel means via smem transpose. Blocks 0..35 emit A-fragments.
// ============================================================
__global__ void __launch_bounds__(256)
k1_stem(const float* __restrict__ X, const float* __restrict__ W,
        const float* __restrict__ bnw, const float* __restrict__ bnb,
        const float* __restrict__ EW) {
    __shared__ __align__(16) float sIn[3 * 18 * 18];
    __shared__ __align__(16) float sW[32 * 28];
    __shared__ float sBw[32], sBb[32];
    __shared__ float sTr[32 * 257];
    __shared__ float sP2[8 * 32];
    int n = blockIdx.x;
    int b = n / 196, pr = (n % 196) / HP, pc = n % HP;
    int tid = threadIdx.x;

    // bf16 A-fragment permutation fold (36*256 == 9216 entries)
    if (n < 36) {
        int i = n * 256 + tid;
        int lane2 = i & 31;
        int kt = (i >> 5) & 1;
        int mt = (i >> 6) & 1;
        int r  = i >> 7;           // e*9 + s
        int s  = r % 9;
        int e  = r / 9;
        int g = lane2 >> 2, c2 = (lane2 & 3) * 2;
        int m0 = mt * 16 + g;
        int ci0 = kt * 16 + c2;
        const float* base = EW + (size_t)e * 32 * 32 * 9 + s;
        #define AW(co, ci) base[((co) * 32 + (ci)) * 9]
        uint4 v;
        v.x = pack_bf2(AW(m0,     ci0),     AW(m0,     ci0 + 1));
        v.y = pack_bf2(AW(m0 + 8, ci0),     AW(m0 + 8, ci0 + 1));
        v.z = pack_bf2(AW(m0,     ci0 + 8), AW(m0,     ci0 + 9));
        v.w = pack_bf2(AW(m0 + 8, ci0 + 8), AW(m0 + 8, ci0 + 9));
        #undef AW
        g_aw2[i] = v;
    }

    for (int i = tid; i < 3 * 18 * 18; i += 256) {
        int ci = i / 324, r = (i % 324) / 18, c = i % 18;
        int gy = pr * 16 + r - 1, gx = pc * 16 + c - 1;
        float v = 0.f;
        if (gy >= 0 && gy < HWD && gx >= 0 && gx < HWD)
            v = X[((b * 3 + ci) * HWD + gy) * HWD + gx];
        sIn[i] = v;
    }
    for (int i = tid; i < 32 * 28; i += 256) {
        int co = i / 28, k = i % 28;
        sW[i] = (k < 27) ? W[co * 27 + k] : 0.f;
    }
    if (tid < 32) { sBw[tid] = bnw[tid]; sBb[tid] = bnb[tid]; }
    __syncthreads();

    int py = tid >> 4, px = tid & 15;
    float xin[28];
#pragma unroll
    for (int ci = 0; ci < 3; ci++)
#pragma unroll
        for (int dy = 0; dy < 3; dy++)
#pragma unroll
            for (int dx = 0; dx < 3; dx++)
                xin[ci * 9 + dy * 3 + dx] = sIn[ci * 324 + (py + dy) * 18 + (px + dx)];
    xin[27] = 0.f;
    u64 xp[14];
#pragma unroll
    for (int j = 0; j < 14; j++) xp[j] = pack2(xin[2 * j], xin[2 * j + 1]);

    unsigned* tok = g_tok32 + (size_t)n * 16 * NPIX + tid;
    for (int cp = 0; cp < 16; cp++) {
        const ulonglong2* w0 = (const ulonglong2*)(sW + (2 * cp) * 28);
        const ulonglong2* w1 = (const ulonglong2*)(sW + (2 * cp + 1) * 28);
        u64 acc0 = 0ULL, acc1 = 0ULL;
#pragma unroll
        for (int j = 0; j < 7; j++) {
            ulonglong2 wa = w0[j], wb = w1[j];
            acc0 = ffma2(wa.x, xp[2 * j], acc0);
            acc0 = ffma2(wa.y, xp[2 * j + 1], acc0);
            acc1 = ffma2(wb.x, xp[2 * j], acc1);
            acc1 = ffma2(wb.y, xp[2 * j + 1], acc1);
        }
        float a0, a1, b0, b1;
        unpack2(acc0, a0, a1);
        unpack2(acc1, b0, b1);
        float v0 = (a0 + a1) * sBw[2 * cp] + sBb[2 * cp];
        float v1 = (b0 + b1) * sBw[2 * cp + 1] + sBb[2 * cp + 1];
        float s0 = v0 / (1.f + __expf(-v0));
        float s1 = v1 / (1.f + __expf(-v1));
        tok[cp * NPIX] = pack_bf2(s0, s1);
        sTr[(2 * cp) * 257 + tid] = s0;
        sTr[(2 * cp + 1) * 257 + tid] = s1;
    }
    __syncthreads();
    // transpose reduction: 32 channels x 8 pixel-slices
    {
        int co2 = tid & 31, j = tid >> 5;
        const float* p = sTr + co2 * 257 + j * 32;
        float sum = 0.f;
#pragma unroll
        for (int k = 0; k < 32; k++) sum += p[k];
        sP2[j * 32 + co2] = sum;
    }
    __syncthreads();
    if (tid < 32) {
        float sum = 0.f;
#pragma unroll
        for (int j = 0; j < 8; j++) sum += sP2[j * 32 + tid];
        g_cmean[n * CH + tid] = sum * (1.f / 256.f);
    }
}

// ============================================================
// K2: gate (one thread/token) + per-block loss partials -> g_lpart
// ============================================================
__global__ void __launch_bounds__(128)
k2_gate(const float* __restrict__ gate_w, const float* __restrict__ gate_b) {
    __shared__ float sGw[50 * 8];
    __shared__ float sGb[8];
    __shared__ float tab[14][9];
    __shared__ float sRed[4][17];
    int tid = threadIdx.x;
    int lane = tid & 31, wid = tid >> 5;

    for (int i = tid; i < 400; i += 128) sGw[i] = gate_w[i];
    if (tid < 8) sGb[tid] = gate_b[tid];
    if (tid < 56) {
        int b2 = tid >> 2, k = tid & 3;
        float f = (float)(1 << k) * PI_F;
        float ss = 0.f, cs = 0.f;
        for (int r = 0; r < 16; r++) {
            float ang = f * ((16.f * b2 + (float)r + 0.5f) / 224.f);
            ss += sinf(ang); cs += cosf(ang);
        }
        tab[b2][1 + 2 * k] = ss * (1.f / 16.f);
        tab[b2][2 + 2 * k] = cs * (1.f / 16.f);
    } else if (tid < 70) {
        int b2 = tid - 56;
        tab[b2][0] = (16.f * b2 + 8.f) / 224.f;
    }
    __syncthreads();

    int n = blockIdx.x * 128 + tid;
    bool act = n < NTOK;
    float part[17];
#pragma unroll
    for (int q = 0; q < 17; q++) part[q] = 0.f;

    if (act) {
        int pr = (n % 196) / HP, pc = n % HP;
        float l[8];
#pragma unroll
        for (int e = 0; e < 8; e++) l[e] = sGb[e];
        const float4* cm4 = (const float4*)&g_cmean[n * CH];
#pragma unroll
        for (int i4 = 0; i4 < 8; i4++) {
            float4 v4 = cm4[i4];
            float vv[4] = {v4.x, v4.y, v4.z, v4.w};
#pragma unroll
            for (int q = 0; q < 4; q++) {
                int i = i4 * 4 + q;
#pragma unroll
                for (int e = 0; e < 8; e++) l[e] = fmaf(vv[q], sGw[i * 8 + e], l[e]);
            }
        }
        {
            float v0 = tab[pr][0], v1 = tab[pc][0];
#pragma unroll
            for (int e = 0; e < 8; e++) {
                l[e] = fmaf(v0, sGw[32 * 8 + e], l[e]);
                l[e] = fmaf(v1, sGw[33 * 8 + e], l[e]);
            }
        }
#pragma unroll
        for (int k = 0; k < 4; k++) {
#pragma unroll
            for (int sub = 0; sub < 4; sub++) {
                float v = (sub < 2) ? tab[pr][1 + 2 * k + sub] : tab[pc][1 + 2 * k + (sub - 2)];
#pragma unroll
                for (int e = 0; e < 8; e++)
                    l[e] = fmaf(v, sGw[(34 + 4 * k + sub) * 8 + e], l[e]);
            }
        }
        float mx = l[0]; int am = 0;
#pragma unroll
        for (int e = 1; e < 8; e++) if (l[e] > mx) { mx = l[e]; am = e; }
        float pe[8], se = 0.f;
#pragma unroll
        for (int e = 0; e < 8; e++) { pe[e] = __expf(l[e] - mx); se += pe[e]; }
        float inv = 1.f / se;
        float lse = mx + __logf(se);
        part[0] = lse * lse;
#pragma unroll
        for (int e = 0; e < 8; e++) part[1 + e] = pe[e] * inv;
        part[9 + am] = 1.f;
        g_top1[n] = am;
        g_ptop[n] = pe[am] * inv;
    }

#pragma unroll
    for (int q = 0; q < 17; q++) {
#pragma unroll
        for (int off = 16; off > 0; off >>= 1)
            part[q] += __shfl_down_sync(0xffffffffu, part[q], off);
        if (lane == 0) sRed[wid][q] = part[q];
    }
    __syncthreads();
    if (tid < 17)
        g_lpart[blockIdx.x * 17 + tid] =
            sRed[0][tid] + sRed[1][tid] + sRed[2][tid] + sRed[3][tid];
}

// ============================================================
// K3: capacity scan (ballot, exact token order) + final losses
// ============================================================
__global__ void __launch_bounds__(512)
k3_dispatch(float* __restrict__ d_out) {
    __shared__ int   sT[NTOK];
    __shared__ int   sWC[16 * 9];
    __shared__ int   sRun[8];
    __shared__ float sRes[17];
    int tid = threadIdx.x;
    int lane = tid & 31, wid = tid >> 5;

    for (int i = tid; i < NTOK; i += 512) sT[i] = g_top1[i];
    if (tid < 8) sRun[tid] = 0;
    if (tid < 144) sWC[tid] = 0;
    if (tid >= 256 && tid < 256 + 17) {
        int q = tid - 256;
        float s = 0.f;
        for (int b2 = 0; b2 < 13; b2++) s += g_lpart[b2 * 17 + q];
        sRes[q] = s;
    }
    __syncthreads();

    for (int c = 0; c < 4; c++) {
        int n = c * 512 + tid;
        bool act = n < NTOK;
        int e = act ? sT[n] : 8;
        unsigned m = __match_any_sync(0xffffffffu, e);
        int lr = __popc(m & ((1u << lane) - 1u));
        if (lr == 0) sWC[wid * 9 + e] = __popc(m);
        __syncthreads();
        if (act) {
            int base = sRun[e];
            for (int w2 = 0; w2 < wid; w2++) base += sWC[w2 * 9 + e];
            int rank = base + lr;
            g_wn[n] = (rank < CAPN) ? g_ptop[n] : 0.f;
        }
        int s = 0;
        if (tid < 8) for (int w2 = 0; w2 < 16; w2++) s += sWC[w2 * 9 + tid];
        __syncthreads();
        if (tid < 8) sRun[tid] += s;
        if (tid < 144) sWC[tid] = 0;
        __syncthreads();
    }

    if (tid == 0) {
        float z = sRes[0] / (float)NTOK;
        float imb = 0.f;
        for (int e = 0; e < 8; e++) imb += sRes[1 + e] * sRes[9 + e];
        imb *= (float)NEXP / ((float)NTOK * (float)NTOK);
        d_out[8000] = z;
        d_out[8001] = imb;
    }
}

// ============================================================
// K4: expert conv3x3 via 9-shift bf16 m16n8k16 tensor-core GEMM.
// 16-byte cp.async pipelined fill (row stride 24, interior at col 4),
// halo-only zero-fill.
// ============================================================
__device__ __forceinline__ void k4_compute_kt(
    const unsigned* __restrict__ sXp, const uint4* __restrict__ aBase,
    const int bIdx[4], int kt, float4 acc[2][4]) {
#pragma unroll
    for (int ky = 0; ky < 3; ky++) {
#pragma unroll
        for (int kx = 0; kx < 3; kx++) {
            const int s = ky * 3 + kx;
            const int off = kt * (8 * PS2) + ky * RS + kx;
            unsigned b0[4], b1[4];
#pragma unroll
            for (int nn = 0; nn < 4; nn++) {
                b0[nn] = sXp[bIdx[nn] + off];
                b1[nn] = sXp[bIdx[nn] + off + 4 * PS2];
            }
#pragma unroll
            for (int mt = 0; mt < 2; mt++) {
                uint4 a = __ldg(aBase + ((s * 2 + mt) * 2 + kt) * 32);
#pragma unroll
                for (int nn = 0; nn < 4; nn++)
                    mma_bf16(acc[mt][nn], a, b0[nn], b1[nn]);
            }
        }
    }
}

__global__ void __launch_bounds__(256, 3)
k4_expert(const float* __restrict__ EB, const float* __restrict__ gamma) {
    __shared__ __align__(16) unsigned sXp[16 * PS2];  // 16 cp-planes, 18 rows x stride 24
    __shared__ float sPs[8][32], sPss[8][32];
    int n = blockIdx.x;
    int tid = threadIdx.x;
    float wn = g_wn[n];
    int e = g_top1[n];
    bool active = (wn != 0.f);
    int wid = tid >> 5, lane = tid & 31;
    int gid = lane >> 2, ctid = lane & 3;

    // async 16B fill: group A = planes 0-7 (it 0,1), group B = planes 8-15 (it 2,3)
    {
        const unsigned* src = g_tok32 + (size_t)n * 16 * NPIX;
        unsigned sbase = (unsigned)__cvta_generic_to_shared(sXp);
#pragma unroll
        for (int it = 0; it < 4; it++) {
            int i = it * 256 + tid;          // u32-quad index (4 px)
            int cp = i >> 6;
            int p = (i & 63) * 4;
            unsigned daddr = sbase +
                (unsigned)(cp * PS2 + ((p >> 4) + 1) * RS + CBASE + (p & 15)) * 4u;
            asm volatile("cp.async.cg.shared.global [%0], [%1], 16;"
                         :: "r"(daddr), "l"(src + i * 4));
            if (it == 1 || it == 3)
                asm volatile("cp.async.commit_group;" ::: "memory");
        }
    }
    // halo-only zero: rows 0/17 cols 3..20, rows 1..16 cols 3 and 20
    for (int i = tid; i < 16 * 68; i += 256) {
        int cp = i / 68, j = i % 68;
        int row, col;
        if (j < 18)      { row = 0;      col = 3 + j; }
        else if (j < 36) { row = 17;     col = 3 + (j - 18); }
        else if (j < 52) { row = j - 35; col = 3; }
        else             { row = j - 51; col = 20; }
        sXp[cp * PS2 + row * RS + col] = 0u;
    }

    asm volatile("cp.async.wait_group 1;" ::: "memory");
    __syncthreads();          // planes 0-7 + halo visible block-wide

    if (!active) {
        asm volatile("cp.async.wait_group 0;" ::: "memory");
        __syncthreads();
        int row = lane >> 1, xb = (lane & 1) * 8;
#pragma unroll
        for (int c4 = 0; c4 < 4; c4++) {
            int co = wid * 4 + c4;
            int cp = co >> 1, par = co & 1;
            const unsigned* tp = sXp + cp * PS2 + (row + 1) * RS + CBASE + xb;
            float s = 0.f, ss = 0.f;
#pragma unroll
            for (int p = 0; p < 8; p++) {
                float v = bf_sel(tp[p], par);
                s += v; ss = fmaf(v, v, ss);
            }
#pragma unroll
            for (int off = 16; off > 0; off >>= 1) {
                s  += __shfl_down_sync(0xffffffffu, s, off);
                ss += __shfl_down_sync(0xffffffffu, ss, off);
            }
            if (lane == 0) { g_psum[n * CH + co] = s; g_psumsq[n * CH + co] = ss; }
        }
        return;
    }

    float4 acc[2][4];
#pragma unroll
    for (int mt = 0; mt < 2; mt++)
#pragma unroll
        for (int nn = 0; nn < 4; nn++) acc[mt][nn] = make_float4(0.f, 0.f, 0.f, 0.f);

    int bIdx[4];
#pragma unroll
    for (int nn = 0; nn < 4; nn++)
        bIdx[nn] = ctid * PS2 + (wid * 2 + (nn >> 1)) * RS + (CBASE - 1) + (nn & 1) * 8 + gid;
    const uint4* aBase = g_aw2 + (size_t)e * 1152 + lane;

    k4_compute_kt(sXp, aBase, bIdx, 0, acc);       // planes 0-7
    asm volatile("cp.async.wait_group 0;" ::: "memory");
    __syncthreads();                               // planes 8-15 visible
    k4_compute_kt(sXp, aBase, bIdx, 1, acc);       // planes 8-15

    // epilogue: y = silu(D + b); v = t + gamma*wn*y; per-(warp,co) partial moments
#pragma unroll
    for (int mt = 0; mt < 2; mt++) {
#pragma unroll
        for (int half = 0; half < 2; half++) {
            int co = mt * 16 + gid + half * 8;
            int cp = co >> 1, par = co & 1;
            float bco = __ldg(EB + e * CH + co);
            float gm = __ldg(gamma + co) * wn;
            float s = 0.f, ss = 0.f;
#pragma unroll
            for (int nn = 0; nn < 4; nn++) {
                float y0 = half ? acc[mt][nn].z : acc[mt][nn].x;
                float y1 = half ? acc[mt][nn].w : acc[mt][nn].y;
                int r = wid * 2 + (nn >> 1);
                int x = (nn & 1) * 8 + 2 * ctid;
                const unsigned* tp = sXp + cp * PS2 + (r + 1) * RS + CBASE + x;
                float t0 = bf_sel(tp[0], par);
                float t1 = bf_sel(tp[1], par);
                float a0 = y0 + bco; a0 = a0 / (1.f + __expf(-a0));
                float a1 = y1 + bco; a1 = a1 / (1.f + __expf(-a1));
                float v0 = t0 + gm * a0;
                float v1 = t1 + gm * a1;
                s += v0 + v1;
                ss = fmaf(v0, v0, ss);
                ss = fmaf(v1, v1, ss);
            }
            s  += __shfl_xor_sync(0xffffffffu, s, 1);
            s  += __shfl_xor_sync(0xffffffffu, s, 2);
            ss += __shfl_xor_sync(0xffffffffu, ss, 1);
            ss += __shfl_xor_sync(0xffffffffu, ss, 2);
            if (ctid == 0) { sPs[wid][co] = s; sPss[wid][co] = ss; }
        }
    }
    __syncthreads();
    if (tid < 32) {
        float S = 0.f, SS = 0.f;
#pragma unroll
        for (int w = 0; w < 8; w++) { S += sPs[w][tid]; SS += sPss[w][tid]; }
        g_psum[n * CH + tid] = S;
        g_psumsq[n * CH + tid] = SS;
    }
}

// ============================================================
// K5: GroupNorm(from moments) + pool + LayerNorm + head
// ============================================================
__global__ void __launch_bounds__(1024)
k5_head(const float* __restrict__ gnw, const float* __restrict__ gnb,
        const float* __restrict__ lnw, const float* __restrict__ lnb,
        const float* __restrict__ hw, const float* __restrict__ hb,
        float* __restrict__ d_out) {
    __shared__ float sS32[32 * 32], sSS32[32 * 32];
    __shared__ float sS[32], sF[32], sFN[32];
    __shared__ float sMg[8], sRg[8];
    int b = blockIdx.x, tid = threadIdx.x;
    {
        int c = tid & 31, sl = tid >> 5;
        float S = 0.f, SS = 0.f;
        for (int t = sl; t < 196; t += 32) {
            int idx = (b * 196 + t) * CH + c;
            S += g_psum[idx]; SS += g_psumsq[idx];
        }
        sS32[sl * 32 + c] = S; sSS32[sl * 32 + c] = SS;
    }
    __syncthreads();
    if (tid < 32) {
        float S = 0.f, SS = 0.f;
#pragma unroll
        for (int sl = 0; sl < 32; sl++) { S += sS32[sl * 32 + tid]; SS += sSS32[sl * 32 + tid]; }
        sS[tid] = S; sS32[tid] = S; sSS32[tid] = SS;
    }
    __syncthreads();
    if (tid < 8) {
        float S  = sS32[tid * 4] + sS32[tid * 4 + 1] + sS32[tid * 4 + 2] + sS32[tid * 4 + 3];
        float SS = sSS32[tid * 4] + sSS32[tid * 4 + 1] + sSS32[tid * 4 + 2] + sSS32[tid * 4 + 3];
        const float inv = 1.f / (4.f * 50176.f);
        float m = S * inv;
        float ex2 = SS * inv;
        sMg[tid] = m;
        sRg[tid] = rsqrtf(ex2 - m * m + EPSV);
    }
    __syncthreads();
    if (tid < 32) {
        float mx = sS[tid] * (1.f / 50176.f);
        int g = tid >> 2;
        sF[tid] = (mx - sMg[g]) * sRg[g] * gnw[tid] + gnb[tid];
    }
    __syncthreads();
    if (tid == 0) {
        float mu = 0.f;
        for (int c = 0; c < 32; c++) mu += sF[c];
        mu *= (1.f / 32.f);
        float va = 0.f;
        for (int c = 0; c < 32; c++) { float d = sF[c] - mu; va = fmaf(d, d, va); }
        va *= (1.f / 32.f);
        float r = rsqrtf(va + EPSV);
        for (int c = 0; c < 32; c++) sFN[c] = (sF[c] - mu) * r * lnw[c] + lnb[c];
    }
    __syncthreads();
    for (int j = tid; j < NCLS; j += 1024) {
        float a = hb[j];
#pragma unroll
        for (int c = 0; c < 32; c++) a = fmaf(sFN[c], hw[c * NCLS + j], a);
        d_out[b * NCLS + j] = a;
    }
}

// ============================================================
extern "C" void kernel_launch(void* const* d_in, const int* in_sizes, int n_in,
                              void* d_out, int out_size) {
    const float* X        = (const float*)d_in[0];
    const float* stem_w   = (const float*)d_in[1];
    const float* bn_w     = (const float*)d_in[2];
    const float* bn_b     = (const float*)d_in[3];
    const float* gate_w   = (const float*)d_in[4];
    const float* gate_b   = (const float*)d_in[5];
    const float* expert_w = (const float*)d_in[6];
    const float* expert_b = (const float*)d_in[7];
    const float* gamma    = (const float*)d_in[8];
    const float* gn_w     = (const float*)d_in[9];
    const float* gn_b     = (const float*)d_in[10];
    const float* ln_w     = (const float*)d_in[11];
    const float* ln_b     = (const float*)d_in[12];
    const float* head_w   = (const float*)d_in[13];
    const float* head_b   = (const float*)d_in[14];
    float* out = (float*)d_out;

    k1_stem<<<NTOK, 256>>>(X, stem_w, bn_w, bn_b, expert_w);
    k2_gate<<<(NTOK + 127) / 128, 128>>>(gate_w, gate_b);
    k3_dispatch<<<1, 512>>>(out);
    k4_expert<<<NTOK, 256>>>(expert_b, gamma);
    k5_head<<<8, 1024>>>(gn_w, gn_b, ln_w, ln_b, head_w, head_b, out);
}